// round 3
// baseline (speedup 1.0000x reference)
#include <cuda_runtime.h>
#include <cuda_bf16.h>
#include <cstdint>

#define BB   8
#define LL   50
#define BL   400
#define MM   32
#define NHOP 2
#define DD   64
#define HH   2
#define HDD  32
#define RR   20
#define NBLK 2

// ---------------- scratch ----------------------------------------------------
__device__ float g_item [BL*DD];
__device__ float g_item0[BL*DD];
__device__ float g_osum [BL*DD];
__device__ float g_V    [BL*RR*DD];
__device__ float g_x    [BL*DD];
__device__ float g_Q    [BL*DD];
__device__ float g_q    [BL*DD];
__device__ float g_k    [BL*DD];
__device__ float g_v    [BL*DD];
__device__ float g_ctx  [BL*DD];

__device__ unsigned g_cnt = 0;
__device__ unsigned g_gen = 0;

__device__ __forceinline__ float lrelu(float x) { return x > 0.f ? x : 0.01f * x; }

// grid-wide barrier: all blocks co-resident (grid sized via occupancy query)
__device__ __forceinline__ void gsync()
{
    __syncthreads();
    if (threadIdx.x == 0) {
        volatile unsigned* genp = &g_gen;
        unsigned gen = *genp;
        __threadfence();
        if (atomicAdd(&g_cnt, 1u) == gridDim.x - 1) {
            g_cnt = 0;
            __threadfence();
            *genp = gen + 1;
        } else {
            while (*genp == gen) __nanosleep(64);
        }
        __threadfence();
    }
    __syncthreads();
}

__global__ __launch_bounds__(256, 2) void k_fused(
    const float* __restrict__ uemb, const float* __restrict__ E,
    const float* __restrict__ rel,  const float* __restrict__ Wt,
    const float* __restrict__ W1,   const float* __restrict__ W2,
    const float* __restrict__ pemb,
    const float* __restrict__ lnas, const float* __restrict__ lnab,
    const float* __restrict__ ipw,  const float* __restrict__ ipb,
    const float* __restrict__ opw,  const float* __restrict__ opb,
    const float* __restrict__ fs,   const float* __restrict__ fb,
    const float* __restrict__ c1w,  const float* __restrict__ c1b,
    const float* __restrict__ c2w,  const float* __restrict__ c2b,
    const float* __restrict__ lls,  const float* __restrict__ llb,
    const int* __restrict__ user, const int* __restrict__ seq,
    const int* __restrict__ pos,  const int* __restrict__ neg,
    const int* __restrict__ mh, const int* __restrict__ mr, const int* __restrict__ mt,
    float* __restrict__ out)
{
    __shared__ __align__(16) float smf[5824];   // 23.3 KB union across phases
    const int t = threadIdx.x;
    const unsigned nb = gridDim.x;

    // ---------- Phase A: init ----------
    for (int idx = blockIdx.x*256 + t; idx < BL*DD; idx += nb*256) {
        int bl = idx >> 6, d = idx & 63;
        float v = E[(long)seq[bl]*DD + d];
        g_item[idx] = v; g_item0[idx] = v; g_osum[idx] = 0.f;
    }
    gsync();

    // ---------- hops ----------
    for (int hop = 0; hop < NHOP; hop++) {
        // Phase B: vcomp. units = (r, chunk-of-25, jhalf) = 20*16*2 = 640
        {
            float* RT = smf;             // 32*68
            float* IT = smf + 32*68;     // 25*64
            for (unsigned u = blockIdx.x; u < 640; u += nb) {
                int r  = u >> 5;
                int c  = (u >> 1) & 15;
                int jh = u & 1;
                const float* Rr = rel + (long)r*4096 + jh*32;
                for (int idx = t; idx < 2048; idx += 256) {
                    int i = idx >> 5, jl = idx & 31;
                    RT[jl*68 + i] = Rr[i*64 + jl];
                }
                int base = c*25*DD;
                for (int idx = t; idx < 25*DD; idx += 256)
                    IT[idx] = g_item[base + idx];
                __syncthreads();

                int jl = t & 31, g = t >> 5;     // g in 0..7
                float4 rt[16];
                const float4* rtj = (const float4*)(RT + jl*68);
                #pragma unroll
                for (int kk = 0; kk < 16; kk++) rt[kk] = rtj[kk];
                int j = jh*32 + jl;
                for (int l = g; l < 25; l += 8) {
                    const float4* iv = (const float4*)(IT + l*DD);
                    float a = 0.f;
                    #pragma unroll
                    for (int kk = 0; kk < 16; kk++) {
                        float4 x = iv[kk];
                        a += rt[kk].x*x.x + rt[kk].y*x.y + rt[kk].z*x.z + rt[kk].w*x.w;
                    }
                    g_V[((long)(c*25 + l)*RR + r)*DD + j] = a;
                }
                __syncthreads();
            }
        }
        gsync();

        // Phase C: hop update. 400 units of 128 threads (2 per block)
        {
            int sub = t >> 7, tt = t & 127;
            float* sc   = smf + sub*320;
            float* pr   = sc + 32;
            float* uu_  = pr + 32;
            float* its  = uu_ + 64;
            float* part = its + 64;
            unsigned stride = nb*2;
            int niter = (BL + stride - 1) / stride;
            for (int it2 = 0; it2 < niter; it2++) {
                unsigned u = blockIdx.x*2 + sub + it2*stride;
                int valid = (u < BL);
                int bl = valid ? (int)u : 0;

                if (tt < DD) its[tt] = g_item[bl*DD + tt];
                int m = tt >> 2, q4 = tt & 3;
                int midx = (bl*NHOP + hop)*MM + m;
                int hid = mh[midx], rid = mr[midx];
                const float4* Vv = (const float4*)(g_V + ((long)bl*RR + rid)*DD) + q4*4;
                const float4* Hh = (const float4*)(E + (long)hid*DD) + q4*4;
                float acc = 0.f;
                #pragma unroll
                for (int i2 = 0; i2 < 4; i2++) {
                    float4 a = Vv[i2], b = Hh[i2];
                    acc += a.x*b.x + a.y*b.y + a.z*b.z + a.w*b.w;
                }
                acc += __shfl_down_sync(0xffffffffu, acc, 2, 4);
                acc += __shfl_down_sync(0xffffffffu, acc, 1, 4);
                if (q4 == 0) sc[m] = acc;
                __syncthreads();

                if (tt < 32) {
                    float v = sc[tt];
                    float mx = v;
                    #pragma unroll
                    for (int o = 16; o; o >>= 1) mx = fmaxf(mx, __shfl_xor_sync(0xffffffffu, mx, o));
                    float e = __expf(v - mx);
                    float s = e;
                    #pragma unroll
                    for (int o = 16; o; o >>= 1) s += __shfl_xor_sync(0xffffffffu, s, o);
                    pr[tt] = e / s;
                }
                __syncthreads();

                int d = tt & 63, half = tt >> 6;
                float od = 0.f;
                #pragma unroll 4
                for (int m2 = half*16; m2 < half*16 + 16; m2++) {
                    int te = mt[(bl*NHOP + hop)*MM + m2];
                    od += pr[m2] * E[(long)te*DD + d];
                }
                part[tt] = od;
                __syncthreads();
                if (tt < DD) {
                    float o = part[tt] + part[tt + 64];
                    if (valid) g_osum[bl*DD + tt] += o;
                    uu_[tt] = o + its[tt];
                }
                __syncthreads();

                if (hop != NHOP - 1) {
                    const float4* wr = (const float4*)(Wt + d*DD) + half*8;
                    const float4* uv = (const float4*)uu_ + half*8;
                    float a = 0.f;
                    #pragma unroll
                    for (int kk = 0; kk < 8; kk++) {
                        float4 w = wr[kk], x = uv[kk];
                        a += w.x*x.x + w.y*x.y + w.z*x.z + w.w*x.w;
                    }
                    part[tt] = a;
                    __syncthreads();
                    if (tt < DD && valid)
                        g_item[bl*DD + tt] = lrelu(part[tt] + part[tt + 64]);
                }
                __syncthreads();
            }
        }
        gsync();
    }

    // ---------- Phase D: interest scan (blocks 0..7) ----------
    if (blockIdx.x < BB) {
        int b = blockIdx.x;
        float* S  = smf;          // 3200
        float* AB = smf + 3200;   // 128
        float* T  = smf + 3328;   // 128
        int i = t & 63, quarter = t >> 6;

        float4 wv[16];
        if (quarter < 2) {
            const float* W = quarter ? W2 : W1;
            const float4* wr = (const float4*)(W + i*DD);
            #pragma unroll
            for (int kk = 0; kk < 16; kk++) wv[kk] = wr[kk];
        }
        for (int idx = t; idx < LL*DD; idx += 256)
            S[idx] = g_item0[b*LL*DD + idx] + g_osum[b*LL*DD + idx];
        float c = 0.f;
        if (quarter < 2) c = uemb[(long)user[b]*DD + i];
        __syncthreads();

        for (int st = 0; st < LL; st++) {
            if (quarter < 2) {
                float sv = S[st*DD + i];
                AB[quarter*64 + i] = quarter ? (sv * c) : (sv + c);
            }
            __syncthreads();
            if (quarter < 2) {
                const float4* in = (const float4*)(AB + quarter*64);
                float a0 = 0.f, a1 = 0.f, a2 = 0.f, a3 = 0.f;
                #pragma unroll
                for (int kk = 0; kk < 16; kk += 4) {
                    float4 x0 = in[kk],   x1 = in[kk+1], x2 = in[kk+2], x3 = in[kk+3];
                    a0 += wv[kk  ].x*x0.x + wv[kk  ].y*x0.y + wv[kk  ].z*x0.z + wv[kk  ].w*x0.w;
                    a1 += wv[kk+1].x*x1.x + wv[kk+1].y*x1.y + wv[kk+1].z*x1.z + wv[kk+1].w*x1.w;
                    a2 += wv[kk+2].x*x2.x + wv[kk+2].y*x2.y + wv[kk+2].z*x2.z + wv[kk+2].w*x2.w;
                    a3 += wv[kk+3].x*x3.x + wv[kk+3].y*x3.y + wv[kk+3].z*x3.z + wv[kk+3].w*x3.w;
                }
                T[quarter*64 + i] = lrelu((a0 + a1) + (a2 + a3));
            }
            __syncthreads();
            if (quarter < 2) {
                float o2 = T[i] + T[64 + i];
                c = o2;
                if (quarter == 0)
                    g_x[(b*LL + st)*DD + i] = o2 * 8.0f + pemb[st*DD + i];
            }
            __syncthreads();
        }
    }
    gsync();

    // ---------- transformer blocks ----------
    for (int bb = 0; bb < NBLK; bb++) {
        // Phase E: LN + qkv proj (400 units of 128 threads)
        {
            int sub = t >> 7, tt = t & 127;
            float* xs = smf + sub*144;
            float* Qs = xs + 64;
            float* mv = Qs + 64;
            unsigned stride = nb*2;
            int niter = (BL + stride - 1) / stride;
            for (int it2 = 0; it2 < niter; it2++) {
                unsigned u = blockIdx.x*2 + sub + it2*stride;
                int valid = (u < BL);
                int bl = valid ? (int)u : 0;
                if (tt < DD) xs[tt] = g_x[bl*DD + tt];
                __syncthreads();
                if (tt < 32) {
                    float s = xs[tt] + xs[tt + 32];
                    #pragma unroll
                    for (int o = 16; o; o >>= 1) s += __shfl_xor_sync(0xffffffffu, s, o);
                    float mean = s * (1.f/64.f);
                    float d0 = xs[tt] - mean, d1 = xs[tt+32] - mean;
                    float vs = d0*d0 + d1*d1;
                    #pragma unroll
                    for (int o = 16; o; o >>= 1) vs += __shfl_xor_sync(0xffffffffu, vs, o);
                    if (tt == 0) { mv[0] = mean; mv[1] = rsqrtf(vs*(1.f/64.f) + 1e-8f); }
                }
                __syncthreads();
                if (tt < DD) {
                    float q = (xs[tt] - mv[0]) * mv[1] * lnas[bb*DD + tt] + lnab[bb*DD + tt];
                    Qs[tt] = q;
                    if (valid) g_Q[bl*DD + tt] = q;
                }
                __syncthreads();
                for (int o = tt; o < 3*DD; o += 128) {
                    const float* src = (o < DD) ? Qs : xs;
                    const float4* w4 = (const float4*)(ipw + ((long)bb*3*DD + o)*DD);
                    const float4* s4 = (const float4*)src;
                    float acc = 0.f;
                    #pragma unroll
                    for (int kk = 0; kk < 16; kk++) {
                        float4 w = w4[kk], x = s4[kk];
                        acc += w.x*x.x + w.y*x.y + w.z*x.z + w.w*x.w;
                    }
                    acc += ipb[bb*3*DD + o];
                    if (valid) {
                        if      (o < DD)   g_q[bl*DD + o      ] = acc;
                        else if (o < 2*DD) g_k[bl*DD + o - 64 ] = acc;
                        else               g_v[bl*DD + o - 128] = acc;
                    }
                }
                __syncthreads();
            }
        }
        gsync();

        // Phase F: attention (blocks 0..15)
        if (blockIdx.x < BB*HH) {
            float* qh = smf;            // 50*36
            float* kh = smf + 1800;
            float* vh = smf + 3600;
            float* ps = smf + 5400;     // 8*52
            int blk = blockIdx.x, b = blk >> 1, h = blk & 1;
            for (int idx = t; idx < LL*HDD; idx += 256) {
                int l = idx >> 5, d = idx & 31;
                int src = (b*LL + l)*DD + h*HDD + d;
                qh[l*36 + d] = g_q[src];
                kh[l*36 + d] = g_k[src];
                vh[l*36 + d] = g_v[src];
            }
            __syncthreads();
            int w = t >> 5, lane = t & 31;
            const float scl = 0.17677669529663687f;
            for (int qi = w; qi < LL; qi += 8) {
                float4 qreg[8];
                const float4* qa = (const float4*)(qh + qi*36);
                #pragma unroll
                for (int kk = 0; kk < 8; kk++) qreg[kk] = qa[kk];
                int k0 = lane, k1 = lane + 32;
                float s0 = -3.0e38f, s1 = -3.0e38f;
                if (k0 <= qi) {
                    const float4* ka = (const float4*)(kh + k0*36);
                    float a = 0.f;
                    #pragma unroll
                    for (int kk = 0; kk < 8; kk++) {
                        float4 kv = ka[kk];
                        a += qreg[kk].x*kv.x + qreg[kk].y*kv.y + qreg[kk].z*kv.z + qreg[kk].w*kv.w;
                    }
                    s0 = a * scl;
                }
                if (k1 <= qi) {
                    const float4* ka = (const float4*)(kh + k1*36);
                    float a = 0.f;
                    #pragma unroll
                    for (int kk = 0; kk < 8; kk++) {
                        float4 kv = ka[kk];
                        a += qreg[kk].x*kv.x + qreg[kk].y*kv.y + qreg[kk].z*kv.z + qreg[kk].w*kv.w;
                    }
                    s1 = a * scl;
                }
                float mx = fmaxf(s0, s1);
                #pragma unroll
                for (int o = 16; o; o >>= 1) mx = fmaxf(mx, __shfl_xor_sync(0xffffffffu, mx, o));
                float e0 = (k0 <= qi) ? __expf(s0 - mx) : 0.f;
                float e1 = (k1 <= qi) ? __expf(s1 - mx) : 0.f;
                float sm = e0 + e1;
                #pragma unroll
                for (int o = 16; o; o >>= 1) sm += __shfl_xor_sync(0xffffffffu, sm, o);
                float inv = 1.f / sm;
                ps[w*52 + k0] = e0 * inv;
                if (k1 < LL) ps[w*52 + k1] = e1 * inv;
                __syncwarp();
                float acc = 0.f;
                for (int kj = 0; kj <= qi; kj++)
                    acc += ps[w*52 + kj] * vh[kj*36 + lane];
                g_ctx[(b*LL + qi)*DD + h*HDD + lane] = acc;
                __syncwarp();
            }
        }
        gsync();

        // Phase G: out-proj + residual + LN + FFN (400 units of 128)
        {
            int sub = t >> 7, tt = t & 127;
            float* cs   = smf + sub*400;
            float* xr   = cs + 64;
            float* x2   = cs + 128;
            float* hdn  = cs + 192;
            float* part = cs + 256;
            float* mv   = cs + 384;
            int i = tt & 63, half = tt >> 6;
            unsigned stride = nb*2;
            int niter = (BL + stride - 1) / stride;
            for (int it2 = 0; it2 < niter; it2++) {
                unsigned u = blockIdx.x*2 + sub + it2*stride;
                int valid = (u < BL);
                int bl = valid ? (int)u : 0;
                if (tt < DD) cs[tt] = g_ctx[bl*DD + tt];
                __syncthreads();
                {
                    const float4* wr = (const float4*)(opw + ((long)bb*DD + i)*DD) + half*8;
                    const float4* uu = (const float4*)cs + half*8;
                    float a = 0.f;
                    #pragma unroll
                    for (int kk = 0; kk < 8; kk++) {
                        float4 w = wr[kk], x = uu[kk];
                        a += w.x*x.x + w.y*x.y + w.z*x.z + w.w*x.w;
                    }
                    part[tt] = a;
                }
                __syncthreads();
                if (tt < DD)
                    xr[tt] = part[tt] + part[tt+64] + opb[bb*DD + tt] + g_Q[bl*DD + tt];
                __syncthreads();
                if (tt < 32) {
                    float s = xr[tt] + xr[tt+32];
                    #pragma unroll
                    for (int o = 16; o; o >>= 1) s += __shfl_xor_sync(0xffffffffu, s, o);
                    float mean = s * (1.f/64.f);
                    float d0 = xr[tt]-mean, d1 = xr[tt+32]-mean;
                    float vs = d0*d0 + d1*d1;
                    #pragma unroll
                    for (int o = 16; o; o >>= 1) vs += __shfl_xor_sync(0xffffffffu, vs, o);
                    if (tt == 0) { mv[0] = mean; mv[1] = rsqrtf(vs*(1.f/64.f) + 1e-8f); }
                }
                __syncthreads();
                if (tt < DD)
                    x2[tt] = (xr[tt] - mv[0]) * mv[1] * fs[bb*DD + tt] + fb[bb*DD + tt];
                __syncthreads();
                {
                    const float4* wr = (const float4*)(c1w + ((long)bb*DD + i)*DD) + half*8;
                    const float4* uu = (const float4*)x2 + half*8;
                    float a = 0.f;
                    #pragma unroll
                    for (int kk = 0; kk < 8; kk++) {
                        float4 w = wr[kk], x = uu[kk];
                        a += w.x*x.x + w.y*x.y + w.z*x.z + w.w*x.w;
                    }
                    part[tt] = a;
                }
                __syncthreads();
                if (tt < DD) {
                    float v = part[tt] + part[tt+64] + c1b[bb*DD + tt];
                    hdn[tt] = v > 0.f ? v : 0.f;
                }
                __syncthreads();
                {
                    const float4* wr = (const float4*)(c2w + ((long)bb*DD + i)*DD) + half*8;
                    const float4* uu = (const float4*)hdn + half*8;
                    float a = 0.f;
                    #pragma unroll
                    for (int kk = 0; kk < 8; kk++) {
                        float4 w = wr[kk], x = uu[kk];
                        a += w.x*x.x + w.y*x.y + w.z*x.z + w.w*x.w;
                    }
                    part[tt] = a;
                }
                __syncthreads();
                if (tt < DD && valid)
                    g_x[bl*DD + tt] = x2[tt] + part[tt] + part[tt+64] + c2b[bb*DD + tt];
                __syncthreads();
            }
        }
        gsync();
    }

    // ---------- Phase H: final LN + logits (400 units of 64 threads) ----------
    {
        int sg = t >> 6, st = t & 63;
        float* xs  = smf + sg*132;
        float* red = xs + 64;
        float* mv  = xs + 128;
        unsigned stride = nb*4;
        int niter = (BL + stride - 1) / stride;
        for (int it2 = 0; it2 < niter; it2++) {
            unsigned u = blockIdx.x*4 + sg + it2*stride;
            int valid = (u < BL);
            int bl = valid ? (int)u : 0;
            xs[st] = g_x[bl*DD + st];
            __syncthreads();
            if (st < 32) {
                float s = xs[st] + xs[st+32];
                #pragma unroll
                for (int o = 16; o; o >>= 1) s += __shfl_xor_sync(0xffffffffu, s, o);
                float mean = s * (1.f/64.f);
                float d0 = xs[st]-mean, d1 = xs[st+32]-mean;
                float vs = d0*d0 + d1*d1;
                #pragma unroll
                for (int o = 16; o; o >>= 1) vs += __shfl_xor_sync(0xffffffffu, vs, o);
                if (st == 0) { mv[0] = mean; mv[1] = rsqrtf(vs*(1.f/64.f) + 1e-8f); }
            }
            __syncthreads();
            float lf = (xs[st] - mv[0]) * mv[1] * lls[st] + llb[st];
            float pe = lf * E[(long)pos[bl]*DD + st];
            float ne = lf * E[(long)neg[bl]*DD + st];
            red[st] = pe;
            __syncthreads();
            if (st < 32) {
                float s = red[st] + red[st+32];
                #pragma unroll
                for (int o = 16; o; o >>= 1) s += __shfl_xor_sync(0xffffffffu, s, o);
                if (st == 0 && valid) out[bl] = s;
            }
            __syncthreads();
            red[st] = ne;
            __syncthreads();
            if (st < 32) {
                float s = red[st] + red[st+32];
                #pragma unroll
                for (int o = 16; o; o >>= 1) s += __shfl_xor_sync(0xffffffffu, s, o);
                if (st == 0 && valid) out[BL + bl] = s;
            }
            __syncthreads();
        }
    }
}

// ---------------- launch ------------------------------------------------------
extern "C" void kernel_launch(void* const* d_in, const int* in_sizes, int n_in,
                              void* d_out, int out_size)
{
    const float* uemb = (const float*)d_in[0];
    const float* E    = (const float*)d_in[1];
    const float* rel  = (const float*)d_in[2];
    const float* Wt   = (const float*)d_in[3];
    const float* W1   = (const float*)d_in[4];
    const float* W2   = (const float*)d_in[5];
    const float* pemb = (const float*)d_in[6];
    const float* lnas = (const float*)d_in[7];
    const float* lnab = (const float*)d_in[8];
    const float* ipw  = (const float*)d_in[9];
    const float* ipb  = (const float*)d_in[10];
    const float* opw  = (const float*)d_in[11];
    const float* opb  = (const float*)d_in[12];
    const float* fs   = (const float*)d_in[13];
    const float* fb   = (const float*)d_in[14];
    const float* c1w  = (const float*)d_in[15];
    const float* c1b  = (const float*)d_in[16];
    const float* c2w  = (const float*)d_in[17];
    const float* c2b  = (const float*)d_in[18];
    const float* lls  = (const float*)d_in[19];
    const float* llb  = (const float*)d_in[20];
    const int*   user = (const int*)d_in[21];
    const int*   seq  = (const int*)d_in[22];
    const int*   pos  = (const int*)d_in[23];
    const int*   neg  = (const int*)d_in[24];
    const int*   mh   = (const int*)d_in[25];
    const int*   mr   = (const int*)d_in[26];
    const int*   mt   = (const int*)d_in[27];
    float* out = (float*)d_out;

    int dev = 0;
    cudaGetDevice(&dev);
    int sms = 0;
    cudaDeviceGetAttribute(&sms, cudaDevAttrMultiProcessorCount, dev);
    int bpm = 0;
    cudaOccupancyMaxActiveBlocksPerMultiprocessor(&bpm, k_fused, 256, 0);
    if (bpm < 1) bpm = 1;
    if (bpm > 2) bpm = 2;
    int grid = sms * bpm;

    k_fused<<<grid, 256>>>(uemb, E, rel, Wt, W1, W2, pemb, lnas, lnab, ipw, ipb,
                           opw, opb, fs, fb, c1w, c1b, c2w, c2b, lls, llb,
                           user, seq, pos, neg, mh, mr, mt, out);
}

// round 4
// speedup vs baseline: 1.3499x; 1.3499x over previous
#include <cuda_runtime.h>
#include <cuda_bf16.h>
#include <cstdint>

#define BB   8
#define LL   50
#define BL   400
#define MM   32
#define NHOP 2
#define DD   64
#define HH   2
#define HDD  32
#define RR   20
#define NBLK 2

// ---------------- scratch ----------------------------------------------------
__device__ float g_item [BL*DD];
__device__ float g_item0[BL*DD];
__device__ float g_osum [BL*DD];
__device__ float g_V    [BL*RR*DD];
__device__ float g_x    [BL*DD];
__device__ float g_Q    [BL*DD];
__device__ float g_q    [BL*DD];
__device__ float g_k    [BL*DD];
__device__ float g_v    [BL*DD];
__device__ float g_ctx  [BL*DD];

__device__ __forceinline__ float lrelu(float x) { return x > 0.f ? x : 0.01f * x; }

// ---------------- K0: item0 = E[seq], item=item0, osum=0 ---------------------
__global__ void k_init(const float* __restrict__ E, const int* __restrict__ seq)
{
    int bl = blockIdx.x, t = threadIdx.x;
    float v = E[(long)seq[bl] * DD + t];
    g_item [bl*DD + t] = v;
    g_item0[bl*DD + t] = v;
    g_osum [bl*DD + t] = 0.f;
}

// ---------------- K1: V[bl,r,j] = sum_i item[bl,i] * R_r[i,j] ----------------
// grid = 640 : unit (r 0..19) x (chunk-of-25 0..15) x (jhalf 0..1). 256 thr.
__global__ __launch_bounds__(256) void k_vcomp2(const float* __restrict__ rel)
{
    __shared__ __align__(16) float RT[32*68];   // RT[jl][i], stride 68
    __shared__ __align__(16) float IT[25*DD];   // 25 item rows
    int u = blockIdx.x;
    int r  = u >> 5;
    int c  = (u >> 1) & 15;
    int jh = u & 1;
    int t = threadIdx.x;

    // transposed load of 32 columns of R_r (columns jh*32..jh*32+31)
    const float* Rr = rel + (long)r*4096 + jh*32;
    for (int idx = t; idx < 2048; idx += 256) {
        int i = idx >> 5, jl = idx & 31;
        RT[jl*68 + i] = Rr[i*64 + jl];
    }
    int base = c * 25 * DD;
    for (int idx = t; idx < 25*DD; idx += 256)
        IT[idx] = g_item[base + idx];
    __syncthreads();

    int jl = t & 31, g = t >> 5;       // g in 0..7, l = g, g+8, g+16, (g+24)
    float4 rt[16];
    const float4* rtj = (const float4*)(RT + jl*68);
    #pragma unroll
    for (int kk = 0; kk < 16; kk++) rt[kk] = rtj[kk];

    int nl = (g == 0) ? 4 : 3;         // g==0 additionally handles l=24
    const float4* it4 = (const float4*)IT;
    float a0 = 0.f, a1 = 0.f, a2 = 0.f, a3 = 0.f;
    #pragma unroll
    for (int kk = 0; kk < 16; kk++) {
        float4 w = rt[kk];
        float4 x0 = it4[(g     )*16 + kk];
        float4 x1 = it4[(g +  8)*16 + kk];
        float4 x2 = it4[(g + 16)*16 + kk];
        a0 += w.x*x0.x + w.y*x0.y + w.z*x0.z + w.w*x0.w;
        a1 += w.x*x1.x + w.y*x1.y + w.z*x1.z + w.w*x1.w;
        a2 += w.x*x2.x + w.y*x2.y + w.z*x2.z + w.w*x2.w;
        if (nl == 4) {
            float4 x3 = it4[24*16 + kk];
            a3 += w.x*x3.x + w.y*x3.y + w.z*x3.z + w.w*x3.w;
        }
    }
    int j = jh*32 + jl;
    g_V[((long)(c*25 + g     )*RR + r)*DD + j] = a0;
    g_V[((long)(c*25 + g +  8)*RR + r)*DD + j] = a1;
    g_V[((long)(c*25 + g + 16)*RR + r)*DD + j] = a2;
    if (nl == 4)
        g_V[((long)(c*25 + 24   )*RR + r)*DD + j] = a3;
}

// ---------------- K2: per-(b,l) hop update -----------------------------------
__global__ __launch_bounds__(128) void k_hop(
    const float* __restrict__ E, const float* __restrict__ Wt,
    const int* __restrict__ mh, const int* __restrict__ mr, const int* __restrict__ mt,
    int hop, int last)
{
    __shared__ float sc[MM], pr[MM], u[DD], part[128], item_s[DD];
    int bl = blockIdx.x, t = threadIdx.x;
    if (t < DD) item_s[t] = g_item[bl*DD + t];

    int m = t >> 2, q4 = t & 3;
    int midx = (bl*NHOP + hop) * MM + m;
    int hid = mh[midx], rid = mr[midx];
    const float4* Vv = (const float4*)(g_V + ((long)bl*RR + rid) * DD) + q4*4;
    const float4* Hh = (const float4*)(E + (long)hid * DD) + q4*4;
    float acc = 0.f;
    #pragma unroll
    for (int i = 0; i < 4; i++) {
        float4 a = Vv[i], b = Hh[i];
        acc += a.x*b.x + a.y*b.y + a.z*b.z + a.w*b.w;
    }
    acc += __shfl_down_sync(0xffffffffu, acc, 2, 4);
    acc += __shfl_down_sync(0xffffffffu, acc, 1, 4);
    if (q4 == 0) sc[m] = acc;
    __syncthreads();

    if (t < 32) {
        float v = sc[t];
        float mx = v;
        #pragma unroll
        for (int o = 16; o; o >>= 1) mx = fmaxf(mx, __shfl_xor_sync(0xffffffffu, mx, o));
        float e = __expf(v - mx);
        float s = e;
        #pragma unroll
        for (int o = 16; o; o >>= 1) s += __shfl_xor_sync(0xffffffffu, s, o);
        pr[t] = e / s;
    }
    __syncthreads();

    int d = t & 63, half = t >> 6;
    float od = 0.f;
    #pragma unroll 4
    for (int m2 = half*16; m2 < half*16 + 16; m2++) {
        int te = mt[(bl*NHOP + hop) * MM + m2];
        od += pr[m2] * E[(long)te * DD + d];
    }
    part[t] = od;
    __syncthreads();
    if (t < DD) {
        float o = part[t] + part[t + 64];
        g_osum[bl*DD + t] += o;
        u[t] = o + item_s[t];
    }
    __syncthreads();

    if (!last) {
        const float4* wr = (const float4*)(Wt + d*DD) + half*8;
        const float4* uu = (const float4*)u + half*8;
        float a = 0.f;
        #pragma unroll
        for (int kk = 0; kk < 8; kk++) {
            float4 w = wr[kk], x = uu[kk];
            a += w.x*x.x + w.y*x.y + w.z*x.z + w.w*x.w;
        }
        part[t] = a;
        __syncthreads();
        if (t < DD) {
            float s = part[t] + part[t + 64];
            g_item[bl*DD + t] = lrelu(s);
        }
    }
}

// ---------------- K3: sequential interest scan (per batch b) -----------------
__global__ __launch_bounds__(128) void k_scan(
    const float* __restrict__ W1, const float* __restrict__ W2,
    const float* __restrict__ uemb, const int* __restrict__ user,
    const float* __restrict__ pemb)
{
    __shared__ float S[LL*DD];
    __shared__ float AB[128];
    __shared__ float T[128];
    int b = blockIdx.x, t = threadIdx.x;
    int i = t & 63, path = t >> 6;

    const float* W = path ? W2 : W1;
    const float4* wr = (const float4*)(W + i*DD);
    float4 wv[16];
    #pragma unroll
    for (int kk = 0; kk < 16; kk++) wv[kk] = wr[kk];

    for (int idx = t; idx < LL*DD; idx += 128)
        S[idx] = g_item0[b*LL*DD + idx] + g_osum[b*LL*DD + idx];

    float c = uemb[(long)user[b] * DD + i];
    __syncthreads();

    for (int st = 0; st < LL; st++) {
        float sv = S[st*DD + i];
        AB[path*64 + i] = path ? (sv * c) : (sv + c);
        __syncthreads();
        const float4* in = (const float4*)(AB + path*64);
        float a0 = 0.f, a1 = 0.f, a2 = 0.f, a3 = 0.f;
        #pragma unroll
        for (int kk = 0; kk < 16; kk += 4) {
            float4 x0 = in[kk],   x1 = in[kk+1], x2 = in[kk+2], x3 = in[kk+3];
            a0 += wv[kk  ].x*x0.x + wv[kk  ].y*x0.y + wv[kk  ].z*x0.z + wv[kk  ].w*x0.w;
            a1 += wv[kk+1].x*x1.x + wv[kk+1].y*x1.y + wv[kk+1].z*x1.z + wv[kk+1].w*x1.w;
            a2 += wv[kk+2].x*x2.x + wv[kk+2].y*x2.y + wv[kk+2].z*x2.z + wv[kk+2].w*x2.w;
            a3 += wv[kk+3].x*x3.x + wv[kk+3].y*x3.y + wv[kk+3].z*x3.z + wv[kk+3].w*x3.w;
        }
        float r = lrelu((a0 + a1) + (a2 + a3));
        T[path*64 + i] = r;
        __syncthreads();
        float out = T[i] + T[64 + i];
        c = out;
        if (path == 0)
            g_x[(b*LL + st)*DD + i] = out * 8.0f + pemb[st*DD + i];
    }
}

// ---------------- K4: per-row LN -> Q, then q/k/v projections ----------------
__global__ __launch_bounds__(128) void k_lnqkv(
    const float* __restrict__ lns, const float* __restrict__ lnb,
    const float* __restrict__ ipw, const float* __restrict__ ipb, int bb)
{
    __shared__ float xs[DD], Qs[DD];
    __shared__ float mv[2];
    int bl = blockIdx.x, t = threadIdx.x;
    if (t < DD) xs[t] = g_x[bl*DD + t];
    __syncthreads();
    if (t < 32) {
        float s = xs[t] + xs[t + 32];
        #pragma unroll
        for (int o = 16; o; o >>= 1) s += __shfl_xor_sync(0xffffffffu, s, o);
        float mean = s * (1.f/64.f);
        float d0 = xs[t] - mean, d1 = xs[t+32] - mean;
        float vs = d0*d0 + d1*d1;
        #pragma unroll
        for (int o = 16; o; o >>= 1) vs += __shfl_xor_sync(0xffffffffu, vs, o);
        if (t == 0) { mv[0] = mean; mv[1] = rsqrtf(vs * (1.f/64.f) + 1e-8f); }
    }
    __syncthreads();
    if (t < DD) {
        float q = (xs[t] - mv[0]) * mv[1] * lns[bb*DD + t] + lnb[bb*DD + t];
        Qs[t] = q;
        g_Q[bl*DD + t] = q;
    }
    __syncthreads();

    for (int o = t; o < 3*DD; o += 128) {
        const float* src = (o < DD) ? Qs : xs;
        const float4* w4 = (const float4*)(ipw + ((long)bb*3*DD + o) * DD);
        const float4* s4 = (const float4*)src;
        float acc = 0.f;
        #pragma unroll
        for (int kk = 0; kk < 16; kk++) {
            float4 w = w4[kk], x = s4[kk];
            acc += w.x*x.x + w.y*x.y + w.z*x.z + w.w*x.w;
        }
        acc += ipb[bb*3*DD + o];
        if      (o < DD)   g_q[bl*DD + o      ] = acc;
        else if (o < 2*DD) g_k[bl*DD + o - 64 ] = acc;
        else               g_v[bl*DD + o - 128] = acc;
    }
}

// ---------------- K5: causal attention, block = (b,h) ------------------------
__global__ __launch_bounds__(256) void k_attn()
{
    __shared__ float qh[LL*36], kh[LL*36], vh[LL*36];
    __shared__ float ps[8][52];
    int blk = blockIdx.x, b = blk >> 1, h = blk & 1, t = threadIdx.x;

    for (int idx = t; idx < LL*HDD; idx += 256) {
        int l = idx >> 5, d = idx & 31;
        int src = (b*LL + l)*DD + h*HDD + d;
        qh[l*36 + d] = g_q[src];
        kh[l*36 + d] = g_k[src];
        vh[l*36 + d] = g_v[src];
    }
    __syncthreads();

    int w = t >> 5, lane = t & 31;
    const float scl = 0.17677669529663687f;
    for (int qi = w; qi < LL; qi += 8) {
        float4 qreg[8];
        const float4* qa = (const float4*)(qh + qi*36);
        #pragma unroll
        for (int kk = 0; kk < 8; kk++) qreg[kk] = qa[kk];

        int k0 = lane, k1 = lane + 32;
        float s0 = -3.0e38f, s1 = -3.0e38f;
        if (k0 <= qi) {
            const float4* ka = (const float4*)(kh + k0*36);
            float a = 0.f;
            #pragma unroll
            for (int kk = 0; kk < 8; kk++) {
                float4 kv = ka[kk];
                a += qreg[kk].x*kv.x + qreg[kk].y*kv.y + qreg[kk].z*kv.z + qreg[kk].w*kv.w;
            }
            s0 = a * scl;
        }
        if (k1 <= qi) {
            const float4* ka = (const float4*)(kh + k1*36);
            float a = 0.f;
            #pragma unroll
            for (int kk = 0; kk < 8; kk++) {
                float4 kv = ka[kk];
                a += qreg[kk].x*kv.x + qreg[kk].y*kv.y + qreg[kk].z*kv.z + qreg[kk].w*kv.w;
            }
            s1 = a * scl;
        }
        float mx = fmaxf(s0, s1);
        #pragma unroll
        for (int o = 16; o; o >>= 1) mx = fmaxf(mx, __shfl_xor_sync(0xffffffffu, mx, o));
        float e0 = (k0 <= qi) ? __expf(s0 - mx) : 0.f;
        float e1 = (k1 <= qi) ? __expf(s1 - mx) : 0.f;
        float sm = e0 + e1;
        #pragma unroll
        for (int o = 16; o; o >>= 1) sm += __shfl_xor_sync(0xffffffffu, sm, o);
        float inv = 1.f / sm;
        ps[w][k0] = e0 * inv;
        if (k1 < LL) ps[w][k1] = e1 * inv;
        __syncwarp();
        float acc = 0.f;
        for (int kj = 0; kj <= qi; kj++)
            acc += ps[w][kj] * vh[kj*36 + lane];
        g_ctx[(b*LL + qi)*DD + h*HDD + lane] = acc;
        __syncwarp();
    }
}

// ---------------- K6: out-proj + residual + LN + FFN (+ final LN/logits) -----
__global__ __launch_bounds__(128) void k_mlp(
    const float* __restrict__ opw, const float* __restrict__ opb,
    const float* __restrict__ fs,  const float* __restrict__ fb,
    const float* __restrict__ c1w, const float* __restrict__ c1b,
    const float* __restrict__ c2w, const float* __restrict__ c2b, int bb,
    int last, const float* __restrict__ E,
    const float* __restrict__ lls, const float* __restrict__ llb,
    const int* __restrict__ pos, const int* __restrict__ neg,
    float* __restrict__ out)
{
    __shared__ float cs[DD], xr[DD], x2[DD], hdn[DD], part[128];
    __shared__ float mv[2];
    int bl = blockIdx.x, t = threadIdx.x;
    int i = t & 63, half = t >> 6;
    if (t < DD) cs[t] = g_ctx[bl*DD + t];
    __syncthreads();

    {
        const float4* wr = (const float4*)(opw + ((long)bb*DD + i)*DD) + half*8;
        const float4* uu = (const float4*)cs + half*8;
        float a = 0.f;
        #pragma unroll
        for (int kk = 0; kk < 8; kk++) {
            float4 w = wr[kk], x = uu[kk];
            a += w.x*x.x + w.y*x.y + w.z*x.z + w.w*x.w;
        }
        part[t] = a;
    }
    __syncthreads();
    if (t < DD)
        xr[t] = part[t] + part[t+64] + opb[bb*DD + t] + g_Q[bl*DD + t];
    __syncthreads();

    if (t < 32) {
        float s = xr[t] + xr[t+32];
        #pragma unroll
        for (int o = 16; o; o >>= 1) s += __shfl_xor_sync(0xffffffffu, s, o);
        float mean = s * (1.f/64.f);
        float d0 = xr[t]-mean, d1 = xr[t+32]-mean;
        float vs = d0*d0 + d1*d1;
        #pragma unroll
        for (int o = 16; o; o >>= 1) vs += __shfl_xor_sync(0xffffffffu, vs, o);
        if (t == 0) { mv[0] = mean; mv[1] = rsqrtf(vs*(1.f/64.f) + 1e-8f); }
    }
    __syncthreads();
    if (t < DD)
        x2[t] = (xr[t] - mv[0]) * mv[1] * fs[bb*DD + t] + fb[bb*DD + t];
    __syncthreads();

    {
        const float4* wr = (const float4*)(c1w + ((long)bb*DD + i)*DD) + half*8;
        const float4* uu = (const float4*)x2 + half*8;
        float a = 0.f;
        #pragma unroll
        for (int kk = 0; kk < 8; kk++) {
            float4 w = wr[kk], x = uu[kk];
            a += w.x*x.x + w.y*x.y + w.z*x.z + w.w*x.w;
        }
        part[t] = a;
    }
    __syncthreads();
    if (t < DD) {
        float v = part[t] + part[t+64] + c1b[bb*DD + t];
        hdn[t] = v > 0.f ? v : 0.f;
    }
    __syncthreads();

    {
        const float4* wr = (const float4*)(c2w + ((long)bb*DD + i)*DD) + half*8;
        const float4* uu = (const float4*)hdn + half*8;
        float a = 0.f;
        #pragma unroll
        for (int kk = 0; kk < 8; kk++) {
            float4 w = wr[kk], x = uu[kk];
            a += w.x*x.x + w.y*x.y + w.z*x.z + w.w*x.w;
        }
        part[t] = a;
    }
    __syncthreads();

    if (!last) {
        if (t < DD)
            g_x[bl*DD + t] = x2[t] + part[t] + part[t+64] + c2b[bb*DD + t];
        return;
    }

    // -------- fused final LN + logits (reuse xr as final x) --------
    if (t < DD)
        xr[t] = x2[t] + part[t] + part[t+64] + c2b[bb*DD + t];
    __syncthreads();
    if (t < 32) {
        float s = xr[t] + xr[t+32];
        #pragma unroll
        for (int o = 16; o; o >>= 1) s += __shfl_xor_sync(0xffffffffu, s, o);
        float mean = s * (1.f/64.f);
        float d0 = xr[t]-mean, d1 = xr[t+32]-mean;
        float vs = d0*d0 + d1*d1;
        #pragma unroll
        for (int o = 16; o; o >>= 1) vs += __shfl_xor_sync(0xffffffffu, vs, o);
        if (t == 0) { mv[0] = mean; mv[1] = rsqrtf(vs*(1.f/64.f) + 1e-8f); }
    }
    __syncthreads();
    if (t < DD) {
        float lf = (xr[t] - mv[0]) * mv[1] * lls[t] + llb[t];
        part[t]      = lf * E[(long)pos[bl]*DD + t];
        part[t + 64] = lf * E[(long)neg[bl]*DD + t];
    }
    __syncthreads();
    if (t < 32) {
        float s = part[t] + part[t+32];
        #pragma unroll
        for (int o = 16; o; o >>= 1) s += __shfl_xor_sync(0xffffffffu, s, o);
        if (t == 0) out[bl] = s;
    } else if (t < 64) {
        int tn = t - 32;
        float s = part[64 + tn] + part[96 + tn];
        #pragma unroll
        for (int o = 16; o; o >>= 1) s += __shfl_xor_sync(0xffffffffu, s, o);
        if (tn == 0) out[BL + bl] = s;
    }
}

// ---------------- launch ------------------------------------------------------
extern "C" void kernel_launch(void* const* d_in, const int* in_sizes, int n_in,
                              void* d_out, int out_size)
{
    const float* uemb = (const float*)d_in[0];
    const float* E    = (const float*)d_in[1];
    const float* rel  = (const float*)d_in[2];
    const float* Wt   = (const float*)d_in[3];
    const float* W1   = (const float*)d_in[4];
    const float* W2   = (const float*)d_in[5];
    const float* pemb = (const float*)d_in[6];
    const float* lnas = (const float*)d_in[7];
    const float* lnab = (const float*)d_in[8];
    const float* ipw  = (const float*)d_in[9];
    const float* ipb  = (const float*)d_in[10];
    const float* opw  = (const float*)d_in[11];
    const float* opb  = (const float*)d_in[12];
    const float* fs   = (const float*)d_in[13];
    const float* fb   = (const float*)d_in[14];
    const float* c1w  = (const float*)d_in[15];
    const float* c1b  = (const float*)d_in[16];
    const float* c2w  = (const float*)d_in[17];
    const float* c2b  = (const float*)d_in[18];
    const float* lls  = (const float*)d_in[19];
    const float* llb  = (const float*)d_in[20];
    const int*   user = (const int*)d_in[21];
    const int*   seq  = (const int*)d_in[22];
    const int*   pos  = (const int*)d_in[23];
    const int*   neg  = (const int*)d_in[24];
    const int*   mh   = (const int*)d_in[25];
    const int*   mr   = (const int*)d_in[26];
    const int*   mt   = (const int*)d_in[27];
    float* out = (float*)d_out;

    k_init<<<BL, 64>>>(E, seq);
    for (int hop = 0; hop < NHOP; hop++) {
        k_vcomp2<<<640, 256>>>(rel);
        k_hop<<<BL, 128>>>(E, Wt, mh, mr, mt, hop, hop == NHOP - 1);
    }
    k_scan<<<BB, 128>>>(W1, W2, uemb, user, pemb);
    for (int bb = 0; bb < NBLK; bb++) {
        k_lnqkv<<<BL, 128>>>(lnas, lnab, ipw, ipb, bb);
        k_attn<<<BB*HH, 256>>>();
        k_mlp<<<BL, 128>>>(opw, opb, fs, fb, c1w, c1b, c2w, c2b, bb,
                           bb == NBLK - 1, E, lls, llb, pos, neg, out);
    }
}